// round 4
// baseline (speedup 1.0000x reference)
#include <cuda_runtime.h>
#include <math.h>

// Problem constants
#define TT 1000
#define BB 32
#define NN 2048
#define BN (BB * NN)            // 65536
#define TSEG 250                // timesteps per segment (4 segments)
#define UU 10                   // prefetch group (250 = 25 * 10)
// Output layout (concatenated tuple, all f32):
#define OFF_FR 0
#define OFF_CV 65536
#define OFF_SY 131072
#define OFF_TS 131104
#define OFF_AN 196640

// Scratch (fully overwritten every launch; no init needed)
__device__ float g_pop_part[1024 * TSEG];   // [b][tseg][chunk][tl]
__device__ int4  g_isi[1024 * 256];         // [b][tseg][chunk][tid] = {first,last,total,sumg2}
__device__ float g_active_part[256];        // per (b,chunk) active-neuron partials

// ---------------------------------------------------------------------------
// Kernel 1: stream the input once. grid = 32b x 4tseg x 8chunk = 1024 blocks.
// ---------------------------------------------------------------------------
__global__ __launch_bounds__(256, 4)
void spike_main(const float* __restrict__ in) {
    const int bid   = blockIdx.x;          // 0..1023
    const int b     = bid >> 5;            // batch
    const int tseg  = (bid >> 3) & 3;      // time segment
    const int chunk = bid & 7;             // neuron chunk
    const int tid   = threadIdx.x;
    const int n     = (chunk << 8) | tid;
    const int w     = tid >> 5;
    const int lane  = tid & 31;
    const int tbase = tseg * TSEG;

    __shared__ float pop_s[8][TSEG];       // 8 KB

    const float* p = in + (size_t)tbase * BN + (size_t)b * NN + n;

    int last = -1, first = -1, total = 0, sumg2 = 0;

    float cur[UU], nxt[UU];
    #pragma unroll
    for (int i = 0; i < UU; i++) cur[i] = p[(size_t)i * BN];

    #pragma unroll 1
    for (int tl0 = 0; tl0 < TSEG; tl0 += UU) {
        const int tn = tl0 + UU;
        if (tn < TSEG) {
            #pragma unroll
            for (int i = 0; i < UU; i++) nxt[i] = p[(size_t)(tn + i) * BN];
        }
        #pragma unroll
        for (int j = 0; j < UU; j++) {
            const int tl = tl0 + j;
            bool s = cur[j] > 0.5f;
            unsigned m = __ballot_sync(0xffffffffu, s);
            if (lane == 0) pop_s[w][tl] = (float)__popc(m);
            if (s) {
                const int t = tbase + tl;          // global timestep
                if (last >= 0) {
                    int g = t - last;
                    sumg2 += g * g;
                } else {
                    first = t;
                }
                last = t;
                total++;
            }
        }
        #pragma unroll
        for (int i = 0; i < UU; i++) cur[i] = nxt[i];
    }

    // Per-thread segment ISI stats -> scratch
    g_isi[bid * 256 + tid] = make_int4(first, last, total, sumg2);

    __syncthreads();
    // Reduce 8 warp rows -> per-block population partial
    if (tid < TSEG) {
        float s = 0.0f;
        #pragma unroll
        for (int k = 0; k < 8; k++) s += pop_s[k][tid];
        g_pop_part[bid * TSEG + tid] = s;
    }
}

// ---------------------------------------------------------------------------
// Kernel 2: merge 4 time segments per neuron, emit per-neuron outputs.
// grid = 32b x 8chunk = 256 blocks, 256 threads (one per neuron).
// ---------------------------------------------------------------------------
__global__ __launch_bounds__(256)
void spike_merge(float* __restrict__ out) {
    const int bid   = blockIdx.x;          // 0..255
    const int b     = bid >> 3;
    const int chunk = bid & 7;
    const int tid   = threadIdx.x;
    const int n     = (chunk << 8) | tid;
    const int w     = tid >> 5;
    const int lane  = tid & 31;

    __shared__ int active_s[8];

    // Load 4 segment records (coalesced: adjacent tid -> adjacent int4)
    int4 segs[4];
    #pragma unroll
    for (int sgi = 0; sgi < 4; sgi++)
        segs[sgi] = g_isi[(((b * 4 + sgi) * 8 + chunk) << 8) + tid];

    int first = -1, last = -1, total = 0, sumg2 = 0;
    #pragma unroll
    for (int sgi = 0; sgi < 4; sgi++) {
        int4 v = segs[sgi];
        if (v.z > 0) {
            if (total > 0) {
                int g = v.x - last;      // boundary gap
                sumg2 += g * g;
            } else {
                first = v.x;
            }
            last   = v.y;
            total += v.z;
            sumg2 += v.w;
        }
    }

    const int idx = b * NN + n;
    float tot = (float)total;
    out[OFF_FR + idx] = tot / (TT * 0.001f);
    out[OFF_TS + idx] = tot;

    float cv = 0.0f;
    int cnt = total - 1;
    if (cnt >= 1) {
        float fc   = (float)cnt;
        float mean = (float)(last - first) / fc;
        float var  = ((float)sumg2 - fc * mean * mean) / fmaxf(fc - 1.0f, 1.0f);
        cv = sqrtf(fmaxf(var, 0.0f)) / fmaxf(mean, 1e-12f);
    }
    out[OFF_CV + idx] = cv;

    unsigned am = __ballot_sync(0xffffffffu, total > 0);
    if (lane == 0) active_s[w] = __popc(am);
    __syncthreads();
    if (tid == 0) {
        int a = 0;
        #pragma unroll
        for (int k = 0; k < 8; k++) a += active_s[k];
        g_active_part[bid] = (float)a;
    }
}

// ---------------------------------------------------------------------------
// Kernel 3: per-batch population autocorrelation + active count. grid = 32.
// num = Sc - S1^2/T, den = S2 - S1^2/T  (circular lag-1, one pass)
// ---------------------------------------------------------------------------
__global__ __launch_bounds__(256)
void spike_sync(float* __restrict__ out) {
    const int b    = blockIdx.x;    // 0..31
    const int tid  = threadIdx.x;
    const int w    = tid >> 5;
    const int lane = tid & 31;

    __shared__ float  pop[TT];
    __shared__ double red1[8], red2[8], redc[8];

    // Assemble pop: 4 tsegs x (250 of 256 threads), 8 chunk partials each
    #pragma unroll
    for (int ts = 0; ts < 4; ts++) {
        if (tid < TSEG) {
            float s = 0.0f;
            #pragma unroll
            for (int k = 0; k < 8; k++)
                s += g_pop_part[((b * 4 + ts) * 8 + k) * TSEG + tid];
            pop[ts * TSEG + tid] = s;
        }
    }
    __syncthreads();

    double s1 = 0.0, s2 = 0.0, sc = 0.0;
    #pragma unroll
    for (int r = 0; r < 4; r++) {
        int t = tid + r * 256;
        if (t < TT) {
            double x = (double)pop[t];
            int tp = (t == 0) ? (TT - 1) : (t - 1);
            double xp = (double)pop[tp];
            s1 += x;
            s2 += x * x;
            sc += x * xp;
        }
    }
    #pragma unroll
    for (int o = 16; o > 0; o >>= 1) {
        s1 += __shfl_down_sync(0xffffffffu, s1, o);
        s2 += __shfl_down_sync(0xffffffffu, s2, o);
        sc += __shfl_down_sync(0xffffffffu, sc, o);
    }
    if (lane == 0) { red1[w] = s1; red2[w] = s2; redc[w] = sc; }
    __syncthreads();
    if (tid == 0) {
        double S1 = 0.0, S2 = 0.0, Sc = 0.0;
        #pragma unroll
        for (int k = 0; k < 8; k++) { S1 += red1[k]; S2 += red2[k]; Sc += redc[k]; }
        double mt  = S1 * S1 / (double)TT;
        double num = Sc - mt;
        double den = S2 - mt;
        out[OFF_SY + b] = (den > 0.0) ? (float)(num / fmax(den, 1e-12)) : 0.0f;
        float a = 0.0f;
        #pragma unroll
        for (int k = 0; k < 8; k++) a += g_active_part[b * 8 + k];
        out[OFF_AN + b] = a;
    }
}

extern "C" void kernel_launch(void* const* d_in, const int* in_sizes, int n_in,
                              void* d_out, int out_size) {
    const float* in = (const float*)d_in[0];
    float* out = (float*)d_out;
    spike_main<<<1024, 256>>>(in);
    spike_merge<<<256, 256>>>(out);
    spike_sync<<<BB, 256>>>(out);
}